// round 2
// baseline (speedup 1.0000x reference)
#include <cuda_runtime.h>
#include <cstddef>

#define D_MODEL 1024
#define N_HEADS 16
#define HEAD_DIM 64
#define BATCH 2
#define SEQ 2048
#define ROWS (BATCH * SEQ)   // 4096

// Scratch (allocation-free rule: __device__ globals)
__device__ float g_Q[ROWS * D_MODEL];
__device__ float g_K[ROWS * D_MODEL];
__device__ float g_V[ROWS * D_MODEL];
__device__ float g_A[ROWS * D_MODEL];   // merged attention output [b*s, h*dh]

// ---------------------------------------------------------------------------
// SGEMM: C[M,N] = A[M,K] @ B[K,N], row-major, 128x128 tile, BK=16,
// 256 threads, 8x8 per thread with 4+4 split to keep float4 smem loads
// low-conflict. M % 128 == 0, N % 128 == 0, K % 16 == 0 (true here).
// ---------------------------------------------------------------------------
__global__ __launch_bounds__(256) void sgemm128(const float* __restrict__ A,
                                                const float* __restrict__ B,
                                                float* __restrict__ C,
                                                int M, int N, int K) {
    __shared__ float As[16][128];
    __shared__ float Bs[16][128];

    const int tid = threadIdx.x;
    const int tx = tid & 15;
    const int ty = tid >> 4;
    const int bm = blockIdx.y * 128;
    const int bn = blockIdx.x * 128;

    float acc[2][2][4][4];
#pragma unroll
    for (int p = 0; p < 2; p++)
#pragma unroll
        for (int q = 0; q < 2; q++)
#pragma unroll
            for (int i = 0; i < 4; i++)
#pragma unroll
                for (int j = 0; j < 4; j++) acc[p][q][i][j] = 0.0f;

    for (int k0 = 0; k0 < K; k0 += 16) {
#pragma unroll
        for (int it = 0; it < 2; it++) {
            int idx = tid + it * 256;              // 0..511
            // A tile: 128 rows x 16 cols = 512 float4 (4 float4 per row)
            int ar = idx >> 2, ac4 = idx & 3;
            float4 va = *(const float4*)(A + (size_t)(bm + ar) * K + k0 + ac4 * 4);
            As[ac4 * 4 + 0][ar] = va.x;
            As[ac4 * 4 + 1][ar] = va.y;
            As[ac4 * 4 + 2][ar] = va.z;
            As[ac4 * 4 + 3][ar] = va.w;
            // B tile: 16 rows x 128 cols = 512 float4 (32 float4 per row)
            int br = idx >> 5, bc4 = idx & 31;
            float4 vb = *(const float4*)(B + (size_t)(k0 + br) * N + bn + bc4 * 4);
            *(float4*)&Bs[br][bc4 * 4] = vb;
        }
        __syncthreads();

#pragma unroll
        for (int kk = 0; kk < 16; kk++) {
            float a[2][4], b[2][4];
            *(float4*)a[0] = *(const float4*)&As[kk][ty * 4];
            *(float4*)a[1] = *(const float4*)&As[kk][64 + ty * 4];
            *(float4*)b[0] = *(const float4*)&Bs[kk][tx * 4];
            *(float4*)b[1] = *(const float4*)&Bs[kk][64 + tx * 4];
#pragma unroll
            for (int p = 0; p < 2; p++)
#pragma unroll
                for (int q = 0; q < 2; q++)
#pragma unroll
                    for (int i = 0; i < 4; i++)
#pragma unroll
                        for (int j = 0; j < 4; j++)
                            acc[p][q][i][j] += a[p][i] * b[q][j];
        }
        __syncthreads();
    }

#pragma unroll
    for (int p = 0; p < 2; p++)
#pragma unroll
        for (int i = 0; i < 4; i++) {
            int row = bm + p * 64 + ty * 4 + i;
#pragma unroll
            for (int q = 0; q < 2; q++) {
                int col = bn + q * 64 + tx * 4;
                float4 v = make_float4(acc[p][q][i][0], acc[p][q][i][1],
                                       acc[p][q][i][2], acc[p][q][i][3]);
                *(float4*)(C + (size_t)row * N + col) = v;
            }
        }
}

// ---------------------------------------------------------------------------
// Fused causal attention (flash-style, fp32).
// Grid: (32 q-blocks, 32 batch*head). Block: 256 threads (16x16, 4x4 each).
// Tiles: BLOCK_M = BLOCK_N = 64, head_dim = 64.
// Smem (dynamic, 52224 B):
//   Qt[64][68]  Q transposed (d-major)  -> float4 reads in S loop
//   KV[64][68]  K transposed (d-major) for S; reused row-major for V
//   Pt[64][68]  P transposed (k-major)  -> float4 reads in P@V loop
// ---------------------------------------------------------------------------
#define SM_STRIDE 68

__global__ __launch_bounds__(256) void attn_kernel() {
    extern __shared__ float sm[];
    float* Qt = sm;                      // [64][68]
    float* KV = sm + 64 * SM_STRIDE;     // [64][68]
    float* Pt = sm + 2 * 64 * SM_STRIDE; // [64][68]

    const int tid = threadIdx.x;
    const int tx = tid & 15;
    const int ty = tid >> 4;
    const int qb = blockIdx.x;           // 0..31
    const int bh = blockIdx.y;           // 0..31
    const int b = bh >> 4;
    const int h = bh & 15;

    const float* Qg = g_Q + ((size_t)(b * SEQ + qb * 64)) * D_MODEL + h * HEAD_DIM;

    // Load Q tile transposed: Qt[d][r]
#pragma unroll
    for (int it = 0; it < 4; it++) {
        int idx = tid + it * 256;        // 0..1023
        int r = idx >> 4, c4 = idx & 15;
        float4 v = *(const float4*)(Qg + (size_t)r * D_MODEL + c4 * 4);
        Qt[(c4 * 4 + 0) * SM_STRIDE + r] = v.x;
        Qt[(c4 * 4 + 1) * SM_STRIDE + r] = v.y;
        Qt[(c4 * 4 + 2) * SM_STRIDE + r] = v.z;
        Qt[(c4 * 4 + 3) * SM_STRIDE + r] = v.w;
    }

    float m[4], l[4], o[4][4];
#pragma unroll
    for (int i = 0; i < 4; i++) {
        m[i] = -1e30f;
        l[i] = 0.0f;
#pragma unroll
        for (int j = 0; j < 4; j++) o[i][j] = 0.0f;
    }

    const float scale = 0.03125f;        // 1/sqrt(1024)

    for (int kb = 0; kb <= qb; kb++) {
        __syncthreads();                 // prior P@V / Pt reads done

        // Load K tile transposed into KV: KV[d][c]
        const float* Kg = g_K + ((size_t)(b * SEQ + kb * 64)) * D_MODEL + h * HEAD_DIM;
#pragma unroll
        for (int it = 0; it < 4; it++) {
            int idx = tid + it * 256;
            int r = idx >> 4, c4 = idx & 15;
            float4 v = *(const float4*)(Kg + (size_t)r * D_MODEL + c4 * 4);
            KV[(c4 * 4 + 0) * SM_STRIDE + r] = v.x;
            KV[(c4 * 4 + 1) * SM_STRIDE + r] = v.y;
            KV[(c4 * 4 + 2) * SM_STRIDE + r] = v.z;
            KV[(c4 * 4 + 3) * SM_STRIDE + r] = v.w;
        }
        __syncthreads();

        // S = Q @ K^T (4x4 per thread)
        float s[4][4] = {{0.f, 0.f, 0.f, 0.f}, {0.f, 0.f, 0.f, 0.f},
                         {0.f, 0.f, 0.f, 0.f}, {0.f, 0.f, 0.f, 0.f}};
#pragma unroll
        for (int d = 0; d < 64; d++) {
            float4 a = *(const float4*)&Qt[d * SM_STRIDE + ty * 4];
            float4 bb = *(const float4*)&KV[d * SM_STRIDE + tx * 4];
            const float av[4] = {a.x, a.y, a.z, a.w};
            const float bv[4] = {bb.x, bb.y, bb.z, bb.w};
#pragma unroll
            for (int i = 0; i < 4; i++)
#pragma unroll
                for (int j = 0; j < 4; j++) s[i][j] += av[i] * bv[j];
        }

        // scale + causal mask
#pragma unroll
        for (int i = 0; i < 4; i++) {
            int qg = qb * 64 + ty * 4 + i;
#pragma unroll
            for (int j = 0; j < 4; j++) {
                int kg = kb * 64 + tx * 4 + j;
                s[i][j] = (kg > qg) ? -1e30f : s[i][j] * scale;
            }
        }

        // Online softmax (row groups of 16 lanes share ty)
#pragma unroll
        for (int i = 0; i < 4; i++) {
            float rowm = fmaxf(fmaxf(s[i][0], s[i][1]), fmaxf(s[i][2], s[i][3]));
#pragma unroll
            for (int off = 8; off > 0; off >>= 1)
                rowm = fmaxf(rowm, __shfl_xor_sync(0xffffffffu, rowm, off));
            float mn = fmaxf(m[i], rowm);
            float alpha = __expf(m[i] - mn);
            m[i] = mn;
            float rs = 0.0f;
#pragma unroll
            for (int j = 0; j < 4; j++) {
                float p = __expf(s[i][j] - mn);
                s[i][j] = p;
                rs += p;
            }
#pragma unroll
            for (int off = 8; off > 0; off >>= 1)
                rs += __shfl_xor_sync(0xffffffffu, rs, off);
            l[i] = l[i] * alpha + rs;
#pragma unroll
            for (int j = 0; j < 4; j++) o[i][j] *= alpha;
        }

        __syncthreads();                 // everyone done reading K from KV

        // Load V tile row-major into KV: KV[k][d]
        const float* Vg = g_V + ((size_t)(b * SEQ + kb * 64)) * D_MODEL + h * HEAD_DIM;
#pragma unroll
        for (int it = 0; it < 4; it++) {
            int idx = tid + it * 256;
            int r = idx >> 4, c4 = idx & 15;
            float4 v = *(const float4*)(Vg + (size_t)r * D_MODEL + c4 * 4);
            *(float4*)&KV[r * SM_STRIDE + c4 * 4] = v;
        }

        // Write P transposed: Pt[k][r]
#pragma unroll
        for (int j = 0; j < 4; j++) {
            float4 pv = make_float4(s[0][j], s[1][j], s[2][j], s[3][j]);
            *(float4*)&Pt[(tx * 4 + j) * SM_STRIDE + ty * 4] = pv;
        }
        __syncthreads();

        // O += P @ V
#pragma unroll
        for (int k = 0; k < 64; k++) {
            float4 a = *(const float4*)&Pt[k * SM_STRIDE + ty * 4];
            float4 bb = *(const float4*)&KV[k * SM_STRIDE + tx * 4];
            const float av[4] = {a.x, a.y, a.z, a.w};
            const float bv[4] = {bb.x, bb.y, bb.z, bb.w};
#pragma unroll
            for (int i = 0; i < 4; i++)
#pragma unroll
                for (int j = 0; j < 4; j++) o[i][j] += av[i] * bv[j];
        }
    }

    // Epilogue: normalize and store merged layout [b*s, h*dh]
    float* Og = g_A + ((size_t)(b * SEQ + qb * 64)) * D_MODEL + h * HEAD_DIM;
#pragma unroll
    for (int i = 0; i < 4; i++) {
        float inv = 1.0f / l[i];
        float4 v = make_float4(o[i][0] * inv, o[i][1] * inv,
                               o[i][2] * inv, o[i][3] * inv);
        *(float4*)(Og + (size_t)(ty * 4 + i) * D_MODEL + tx * 4) = v;
    }
}

// ---------------------------------------------------------------------------
// kernel_launch
// Inputs (metadata order): x, qw, kw, vw, ow (all float32)
// ---------------------------------------------------------------------------
extern "C" void kernel_launch(void* const* d_in, const int* in_sizes, int n_in,
                              void* d_out, int out_size) {
    const float* x  = (const float*)d_in[0];
    const float* qw = (const float*)d_in[1];
    const float* kw = (const float*)d_in[2];
    const float* vw = (const float*)d_in[3];
    const float* ow = (const float*)d_in[4];
    float* out = (float*)d_out;

    float *Q, *K, *V, *A;
    cudaGetSymbolAddress((void**)&Q, g_Q);
    cudaGetSymbolAddress((void**)&K, g_K);
    cudaGetSymbolAddress((void**)&V, g_V);
    cudaGetSymbolAddress((void**)&A, g_A);

    const int attn_smem = 3 * 64 * SM_STRIDE * (int)sizeof(float);  // 52224 B
    cudaFuncSetAttribute(attn_kernel, cudaFuncAttributeMaxDynamicSharedMemorySize,
                         attn_smem);

    dim3 gemm_grid(D_MODEL / 128, ROWS / 128);  // (8, 32)
    sgemm128<<<gemm_grid, 256>>>(x, qw, Q, ROWS, D_MODEL, D_MODEL);
    sgemm128<<<gemm_grid, 256>>>(x, kw, K, ROWS, D_MODEL, D_MODEL);
    sgemm128<<<gemm_grid, 256>>>(x, vw, V, ROWS, D_MODEL, D_MODEL);

    dim3 attn_grid(SEQ / 64, BATCH * N_HEADS);  // (32, 32)
    attn_kernel<<<attn_grid, 256, attn_smem>>>();

    sgemm128<<<gemm_grid, 256>>>(A, ow, out, ROWS, D_MODEL, D_MODEL);
}

// round 4
// speedup vs baseline: 2.1229x; 2.1229x over previous
#include <cuda_runtime.h>
#include <cuda_bf16.h>
#include <cstdint>
#include <cstddef>

#define D_MODEL 1024
#define N_HEADS 16
#define HEAD_DIM 64
#define BATCH 2
#define SEQ 2048
#define ROWS (BATCH * SEQ)   // 4096

// ---------------- scratch (__device__ globals; allocation-free rule) -------
__device__ float g_Q[ROWS * D_MODEL];
__device__ float g_K[ROWS * D_MODEL];
__device__ float g_V[ROWS * D_MODEL];
__device__ float g_A[ROWS * D_MODEL];

__device__ __nv_bfloat16 g_xh[ROWS * D_MODEL];
__device__ __nv_bfloat16 g_xl[ROWS * D_MODEL];
__device__ __nv_bfloat16 g_ah[ROWS * D_MODEL];
__device__ __nv_bfloat16 g_al[ROWS * D_MODEL];
__device__ __nv_bfloat16 g_wh[4 * D_MODEL * D_MODEL];  // transposed [N,K]
__device__ __nv_bfloat16 g_wl[4 * D_MODEL * D_MODEL];

// ---------------- helpers --------------------------------------------------
__device__ __forceinline__ uint32_t smem_u32(const void* p) {
    uint32_t a;
    asm("{ .reg .u64 t; cvta.to.shared.u64 t, %1; cvt.u32.u64 %0, t; }"
        : "=r"(a) : "l"(p));
    return a;
}

__device__ __forceinline__ void ldsm_x4(uint32_t addr, uint32_t& r0, uint32_t& r1,
                                        uint32_t& r2, uint32_t& r3) {
    asm volatile("ldmatrix.sync.aligned.m8n8.x4.shared.b16 {%0,%1,%2,%3}, [%4];"
                 : "=r"(r0), "=r"(r1), "=r"(r2), "=r"(r3) : "r"(addr));
}

__device__ __forceinline__ void mma16816(float* c, const uint32_t* a, const uint32_t* b) {
    asm volatile(
        "mma.sync.aligned.m16n8k16.row.col.f32.bf16.bf16.f32 "
        "{%0,%1,%2,%3},{%4,%5,%6,%7},{%8,%9},{%0,%1,%2,%3};"
        : "+f"(c[0]), "+f"(c[1]), "+f"(c[2]), "+f"(c[3])
        : "r"(a[0]), "r"(a[1]), "r"(a[2]), "r"(a[3]), "r"(b[0]), "r"(b[1]));
}

// ---------------------------------------------------------------------------
// Split-bf16 GEMM via mma.sync: C[M,N] = (Ah+Al)[M,K] @ (Bh+Bl)^T,
// B given transposed [N,K]. CTA tile 128x128, BK=32, 256 threads (8 warps,
// warp tile m32 x n64). Smem rows padded to 40 halves (80B) => conflict-free
// ldmatrix (banks (20r)%32 distinct over r=0..7).
// Product: Ah*Bh + Al*Bh + Ah*Bl (drop Al*Bl ~ 2^-18).
// ---------------------------------------------------------------------------
#define GK 1024
#define TS 40                        // halves per 32-k row (padded)
#define TILE_HALVES (128 * TS)       // 5120
#define TILE_BYTES (TILE_HALVES * 2) // 10240

__global__ __launch_bounds__(256) void gemm_mma(
    const __nv_bfloat16* __restrict__ Ah, const __nv_bfloat16* __restrict__ Al,
    const __nv_bfloat16* __restrict__ Bh, const __nv_bfloat16* __restrict__ Bl,
    float* __restrict__ C) {
    __shared__ __align__(16) __nv_bfloat16 sm[4][TILE_HALVES];

    const int tid = threadIdx.x;
    const int lane = tid & 31;
    const int wid = tid >> 5;
    const int wm = wid & 3;          // 4 warps along m
    const int wn = wid >> 2;         // 2 warps along n
    const int mBase = wm * 32;
    const int nBase = wn * 64;
    const int bm = blockIdx.y * 128;
    const int bn = blockIdx.x * 128;
    const uint32_t sb = smem_u32(sm);

    float c[2][8][4];
#pragma unroll
    for (int mt = 0; mt < 2; mt++)
#pragma unroll
        for (int nt = 0; nt < 8; nt++)
#pragma unroll
            for (int j = 0; j < 4; j++) c[mt][nt][j] = 0.0f;

    // ldmatrix address components (in bytes)
    const int a_row = lane & 15;                      // source m-row within 16
    const int a_koff = (lane >> 4) * 8;               // k half select
    const int b_nrow = ((lane >> 4) * 8) + (lane & 7);
    const int b_koff = ((lane >> 3) & 1) * 8;

    for (int ch = 0; ch < GK / 32; ch++) {
        const int k0 = ch * 32;
        const __nv_bfloat16* srcs[4] = {
            Ah + (size_t)bm * GK + k0, Al + (size_t)bm * GK + k0,
            Bh + (size_t)bn * GK + k0, Bl + (size_t)bn * GK + k0};
        __syncthreads();
#pragma unroll
        for (int t = 0; t < 4; t++) {
#pragma unroll
            for (int it = 0; it < 2; it++) {
                int idx = tid + it * 256;          // 0..511
                int r = idx >> 2, c16 = idx & 3;   // 4 x 16B per 64B row
                uint4 v = *(const uint4*)(srcs[t] + (size_t)r * GK + c16 * 8);
                *(uint4*)&sm[t][r * TS + c16 * 8] = v;
            }
        }
        __syncthreads();

#pragma unroll
        for (int ks = 0; ks < 2; ks++) {
            uint32_t aH[2][4], aL[2][4], b[8][2];
#pragma unroll
            for (int mt = 0; mt < 2; mt++) {
                uint32_t off = ((mBase + mt * 16 + a_row) * TS + ks * 16 + a_koff) * 2;
                ldsm_x4(sb + off, aH[mt][0], aH[mt][1], aH[mt][2], aH[mt][3]);
                ldsm_x4(sb + TILE_BYTES + off, aL[mt][0], aL[mt][1], aL[mt][2], aL[mt][3]);
            }
            // bH
#pragma unroll
            for (int g = 0; g < 4; g++) {
                uint32_t off = ((nBase + g * 16 + b_nrow) * TS + ks * 16 + b_koff) * 2;
                ldsm_x4(sb + 2 * TILE_BYTES + off,
                        b[2 * g][0], b[2 * g][1], b[2 * g + 1][0], b[2 * g + 1][1]);
            }
#pragma unroll
            for (int mt = 0; mt < 2; mt++)
#pragma unroll
                for (int nt = 0; nt < 8; nt++) mma16816(c[mt][nt], aH[mt], b[nt]);
#pragma unroll
            for (int mt = 0; mt < 2; mt++)
#pragma unroll
                for (int nt = 0; nt < 8; nt++) mma16816(c[mt][nt], aL[mt], b[nt]);
            // bL
#pragma unroll
            for (int g = 0; g < 4; g++) {
                uint32_t off = ((nBase + g * 16 + b_nrow) * TS + ks * 16 + b_koff) * 2;
                ldsm_x4(sb + 3 * TILE_BYTES + off,
                        b[2 * g][0], b[2 * g][1], b[2 * g + 1][0], b[2 * g + 1][1]);
            }
#pragma unroll
            for (int mt = 0; mt < 2; mt++)
#pragma unroll
                for (int nt = 0; nt < 8; nt++) mma16816(c[mt][nt], aH[mt], b[nt]);
        }
    }

    // epilogue
#pragma unroll
    for (int mt = 0; mt < 2; mt++) {
        int row = bm + mBase + mt * 16 + (lane >> 2);
#pragma unroll
        for (int nt = 0; nt < 8; nt++) {
            int col = bn + nBase + nt * 8 + (lane & 3) * 2;
            *(float2*)(C + (size_t)row * D_MODEL + col) = make_float2(c[mt][nt][0], c[mt][nt][1]);
            *(float2*)(C + (size_t)(row + 8) * D_MODEL + col) = make_float2(c[mt][nt][2], c[mt][nt][3]);
        }
    }
}

// ---------------------------------------------------------------------------
// Conversion kernels
// ---------------------------------------------------------------------------
__global__ __launch_bounds__(256) void split_fp32(const float* __restrict__ s,
                                                  __nv_bfloat16* __restrict__ h,
                                                  __nv_bfloat16* __restrict__ l) {
    int i = blockIdx.x * 256 + threadIdx.x;   // one float4 per thread
    float4 v = ((const float4*)s)[i];
    float a[4] = {v.x, v.y, v.z, v.w};
    __nv_bfloat162 hh[2], ll[2];
#pragma unroll
    for (int j = 0; j < 2; j++) {
        __nv_bfloat16 h0 = __float2bfloat16(a[2 * j]);
        __nv_bfloat16 h1 = __float2bfloat16(a[2 * j + 1]);
        __nv_bfloat16 l0 = __float2bfloat16(a[2 * j] - __bfloat162float(h0));
        __nv_bfloat16 l1 = __float2bfloat16(a[2 * j + 1] - __bfloat162float(h1));
        hh[j] = __nv_bfloat162(h0, h1);
        ll[j] = __nv_bfloat162(l0, l1);
    }
    ((__nv_bfloat162*)h)[2 * i] = hh[0];
    ((__nv_bfloat162*)h)[2 * i + 1] = hh[1];
    ((__nv_bfloat162*)l)[2 * i] = ll[0];
    ((__nv_bfloat162*)l)[2 * i + 1] = ll[1];
}

__global__ __launch_bounds__(256) void transpose_split(const float* __restrict__ W,
                                                       __nv_bfloat16* __restrict__ Th,
                                                       __nv_bfloat16* __restrict__ Tl) {
    __shared__ float t[32][33];
    int x = blockIdx.x * 32 + threadIdx.x;   // col n
    int y0 = blockIdx.y * 32;                // row k base
#pragma unroll
    for (int j = 0; j < 32; j += 8)
        t[threadIdx.y + j][threadIdx.x] = W[(size_t)(y0 + threadIdx.y + j) * D_MODEL + x];
    __syncthreads();
    int xo = blockIdx.y * 32 + threadIdx.x;  // k
    int yo = blockIdx.x * 32;                // n base
#pragma unroll
    for (int j = 0; j < 32; j += 8) {
        float v = t[threadIdx.x][threadIdx.y + j];
        __nv_bfloat16 hv = __float2bfloat16(v);
        Th[(size_t)(yo + threadIdx.y + j) * D_MODEL + xo] = hv;
        Tl[(size_t)(yo + threadIdx.y + j) * D_MODEL + xo] =
            __float2bfloat16(v - __bfloat162float(hv));
    }
}

// ---------------------------------------------------------------------------
// Fused causal attention (flash-style, fp32) — unchanged from R2 (verified)
// ---------------------------------------------------------------------------
#define SM_STRIDE 68

__global__ __launch_bounds__(256) void attn_kernel() {
    extern __shared__ float sm[];
    float* Qt = sm;
    float* KV = sm + 64 * SM_STRIDE;
    float* Pt = sm + 2 * 64 * SM_STRIDE;

    const int tid = threadIdx.x;
    const int tx = tid & 15;
    const int ty = tid >> 4;
    const int qb = blockIdx.x;
    const int bh = blockIdx.y;
    const int b = bh >> 4;
    const int h = bh & 15;

    const float* Qg = g_Q + ((size_t)(b * SEQ + qb * 64)) * D_MODEL + h * HEAD_DIM;

#pragma unroll
    for (int it = 0; it < 4; it++) {
        int idx = tid + it * 256;
        int r = idx >> 4, c4 = idx & 15;
        float4 v = *(const float4*)(Qg + (size_t)r * D_MODEL + c4 * 4);
        Qt[(c4 * 4 + 0) * SM_STRIDE + r] = v.x;
        Qt[(c4 * 4 + 1) * SM_STRIDE + r] = v.y;
        Qt[(c4 * 4 + 2) * SM_STRIDE + r] = v.z;
        Qt[(c4 * 4 + 3) * SM_STRIDE + r] = v.w;
    }

    float m[4], l[4], o[4][4];
#pragma unroll
    for (int i = 0; i < 4; i++) {
        m[i] = -1e30f;
        l[i] = 0.0f;
#pragma unroll
        for (int j = 0; j < 4; j++) o[i][j] = 0.0f;
    }

    const float scale = 0.03125f;

    for (int kb = 0; kb <= qb; kb++) {
        __syncthreads();
        const float* Kg = g_K + ((size_t)(b * SEQ + kb * 64)) * D_MODEL + h * HEAD_DIM;
#pragma unroll
        for (int it = 0; it < 4; it++) {
            int idx = tid + it * 256;
            int r = idx >> 4, c4 = idx & 15;
            float4 v = *(const float4*)(Kg + (size_t)r * D_MODEL + c4 * 4);
            KV[(c4 * 4 + 0) * SM_STRIDE + r] = v.x;
            KV[(c4 * 4 + 1) * SM_STRIDE + r] = v.y;
            KV[(c4 * 4 + 2) * SM_STRIDE + r] = v.z;
            KV[(c4 * 4 + 3) * SM_STRIDE + r] = v.w;
        }
        __syncthreads();

        float s[4][4] = {{0.f, 0.f, 0.f, 0.f}, {0.f, 0.f, 0.f, 0.f},
                         {0.f, 0.f, 0.f, 0.f}, {0.f, 0.f, 0.f, 0.f}};
#pragma unroll
        for (int d = 0; d < 64; d++) {
            float4 a = *(const float4*)&Qt[d * SM_STRIDE + ty * 4];
            float4 bb = *(const float4*)&KV[d * SM_STRIDE + tx * 4];
            const float av[4] = {a.x, a.y, a.z, a.w};
            const float bv[4] = {bb.x, bb.y, bb.z, bb.w};
#pragma unroll
            for (int i = 0; i < 4; i++)
#pragma unroll
                for (int j = 0; j < 4; j++) s[i][j] += av[i] * bv[j];
        }

#pragma unroll
        for (int i = 0; i < 4; i++) {
            int qg = qb * 64 + ty * 4 + i;
#pragma unroll
            for (int j = 0; j < 4; j++) {
                int kg = kb * 64 + tx * 4 + j;
                s[i][j] = (kg > qg) ? -1e30f : s[i][j] * scale;
            }
        }

#pragma unroll
        for (int i = 0; i < 4; i++) {
            float rowm = fmaxf(fmaxf(s[i][0], s[i][1]), fmaxf(s[i][2], s[i][3]));
#pragma unroll
            for (int off = 8; off > 0; off >>= 1)
                rowm = fmaxf(rowm, __shfl_xor_sync(0xffffffffu, rowm, off));
            float mn = fmaxf(m[i], rowm);
            float alpha = __expf(m[i] - mn);
            m[i] = mn;
            float rs = 0.0f;
#pragma unroll
            for (int j = 0; j < 4; j++) {
                float p = __expf(s[i][j] - mn);
                s[i][j] = p;
                rs += p;
            }
#pragma unroll
            for (int off = 8; off > 0; off >>= 1)
                rs += __shfl_xor_sync(0xffffffffu, rs, off);
            l[i] = l[i] * alpha + rs;
#pragma unroll
            for (int j = 0; j < 4; j++) o[i][j] *= alpha;
        }

        __syncthreads();

        const float* Vg = g_V + ((size_t)(b * SEQ + kb * 64)) * D_MODEL + h * HEAD_DIM;
#pragma unroll
        for (int it = 0; it < 4; it++) {
            int idx = tid + it * 256;
            int r = idx >> 4, c4 = idx & 15;
            float4 v = *(const float4*)(Vg + (size_t)r * D_MODEL + c4 * 4);
            *(float4*)&KV[r * SM_STRIDE + c4 * 4] = v;
        }

#pragma unroll
        for (int j = 0; j < 4; j++) {
            float4 pv = make_float4(s[0][j], s[1][j], s[2][j], s[3][j]);
            *(float4*)&Pt[(tx * 4 + j) * SM_STRIDE + ty * 4] = pv;
        }
        __syncthreads();

#pragma unroll
        for (int k = 0; k < 64; k++) {
            float4 a = *(const float4*)&Pt[k * SM_STRIDE + ty * 4];
            float4 bb = *(const float4*)&KV[k * SM_STRIDE + tx * 4];
            const float av[4] = {a.x, a.y, a.z, a.w};
            const float bv[4] = {bb.x, bb.y, bb.z, bb.w};
#pragma unroll
            for (int i = 0; i < 4; i++)
#pragma unroll
                for (int j = 0; j < 4; j++) o[i][j] += av[i] * bv[j];
        }
    }

    float* Og = g_A + ((size_t)(b * SEQ + qb * 64)) * D_MODEL + h * HEAD_DIM;
#pragma unroll
    for (int i = 0; i < 4; i++) {
        float inv = 1.0f / l[i];
        float4 v = make_float4(o[i][0] * inv, o[i][1] * inv,
                               o[i][2] * inv, o[i][3] * inv);
        *(float4*)(Og + (size_t)(ty * 4 + i) * D_MODEL + tx * 4) = v;
    }
}

// ---------------------------------------------------------------------------
// kernel_launch: x, qw, kw, vw, ow (fp32)
// ---------------------------------------------------------------------------
extern "C" void kernel_launch(void* const* d_in, const int* in_sizes, int n_in,
                              void* d_out, int out_size) {
    const float* x = (const float*)d_in[0];
    const float* w[4] = {(const float*)d_in[1], (const float*)d_in[2],
                         (const float*)d_in[3], (const float*)d_in[4]};
    float* out = (float*)d_out;

    float *Q, *K, *V, *A;
    __nv_bfloat16 *xh, *xl, *ah, *al, *wh, *wl;
    cudaGetSymbolAddress((void**)&Q, g_Q);
    cudaGetSymbolAddress((void**)&K, g_K);
    cudaGetSymbolAddress((void**)&V, g_V);
    cudaGetSymbolAddress((void**)&A, g_A);
    cudaGetSymbolAddress((void**)&xh, g_xh);
    cudaGetSymbolAddress((void**)&xl, g_xl);
    cudaGetSymbolAddress((void**)&ah, g_ah);
    cudaGetSymbolAddress((void**)&al, g_al);
    cudaGetSymbolAddress((void**)&wh, g_wh);
    cudaGetSymbolAddress((void**)&wl, g_wl);

    const int attn_smem = 3 * 64 * SM_STRIDE * (int)sizeof(float);
    cudaFuncSetAttribute(attn_kernel, cudaFuncAttributeMaxDynamicSharedMemorySize,
                         attn_smem);

    // 1. split x into bf16 hi/lo
    split_fp32<<<(ROWS * D_MODEL / 4) / 256, 256>>>(x, xh, xl);
    // 2. transpose+split weights to [N,K] bf16 hi/lo
    for (int i = 0; i < 4; i++)
        transpose_split<<<dim3(32, 32), dim3(32, 8)>>>(
            w[i], wh + (size_t)i * D_MODEL * D_MODEL, wl + (size_t)i * D_MODEL * D_MODEL);

    // 3. Q/K/V projections (mma.sync split-bf16)
    dim3 ggrid(D_MODEL / 128, ROWS / 128);  // (8, 32)
    gemm_mma<<<ggrid, 256>>>(xh, xl, wh, wl, Q);
    gemm_mma<<<ggrid, 256>>>(xh, xl, wh + 1u * D_MODEL * D_MODEL,
                             wl + 1u * D_MODEL * D_MODEL, K);
    gemm_mma<<<ggrid, 256>>>(xh, xl, wh + 2u * D_MODEL * D_MODEL,
                             wl + 2u * D_MODEL * D_MODEL, V);

    // 4. attention
    dim3 agrid(SEQ / 64, BATCH * N_HEADS);
    attn_kernel<<<agrid, 256, attn_smem>>>();

    // 5. split attention output; 6. output projection
    split_fp32<<<(ROWS * D_MODEL / 4) / 256, 256>>>(A, ah, al);
    gemm_mma<<<ggrid, 256>>>(ah, al, wh + 3u * D_MODEL * D_MODEL,
                             wl + 3u * D_MODEL * D_MODEL, out);
}

// round 5
// speedup vs baseline: 3.6099x; 1.7004x over previous
#include <cuda_runtime.h>
#include <cuda_bf16.h>
#include <cstdint>
#include <cstddef>

#define D_MODEL 1024
#define N_HEADS 16
#define HEAD_DIM 64
#define BATCH 2
#define SEQ 2048
#define ROWS (BATCH * SEQ)   // 4096

// ---------------- scratch (__device__ globals; allocation-free rule) -------
__device__ __nv_bfloat16 g_xh[ROWS * D_MODEL];
__device__ __nv_bfloat16 g_xl[ROWS * D_MODEL];
__device__ __nv_bfloat16 g_qh[ROWS * D_MODEL];
__device__ __nv_bfloat16 g_ql[ROWS * D_MODEL];
__device__ __nv_bfloat16 g_kh[ROWS * D_MODEL];
__device__ __nv_bfloat16 g_kl[ROWS * D_MODEL];
__device__ __nv_bfloat16 g_vh[ROWS * D_MODEL];
__device__ __nv_bfloat16 g_vl[ROWS * D_MODEL];
__device__ __nv_bfloat16 g_ah[ROWS * D_MODEL];
__device__ __nv_bfloat16 g_al[ROWS * D_MODEL];
__device__ __nv_bfloat16 g_wh[4 * D_MODEL * D_MODEL];  // transposed [N,K]
__device__ __nv_bfloat16 g_wl[4 * D_MODEL * D_MODEL];

// ---------------- helpers --------------------------------------------------
__device__ __forceinline__ uint32_t smem_u32(const void* p) {
    uint32_t a;
    asm("{ .reg .u64 t; cvta.to.shared.u64 t, %1; cvt.u32.u64 %0, t; }"
        : "=r"(a) : "l"(p));
    return a;
}

__device__ __forceinline__ void ldsm_x4(uint32_t addr, uint32_t& r0, uint32_t& r1,
                                        uint32_t& r2, uint32_t& r3) {
    asm volatile("ldmatrix.sync.aligned.m8n8.x4.shared.b16 {%0,%1,%2,%3}, [%4];"
                 : "=r"(r0), "=r"(r1), "=r"(r2), "=r"(r3) : "r"(addr));
}

__device__ __forceinline__ void ldsm_x4_t(uint32_t addr, uint32_t& r0, uint32_t& r1,
                                          uint32_t& r2, uint32_t& r3) {
    asm volatile("ldmatrix.sync.aligned.m8n8.x4.trans.shared.b16 {%0,%1,%2,%3}, [%4];"
                 : "=r"(r0), "=r"(r1), "=r"(r2), "=r"(r3) : "r"(addr));
}

__device__ __forceinline__ void mma16816(float* c, const uint32_t* a, const uint32_t* b) {
    asm volatile(
        "mma.sync.aligned.m16n8k16.row.col.f32.bf16.bf16.f32 "
        "{%0,%1,%2,%3},{%4,%5,%6,%7},{%8,%9},{%0,%1,%2,%3};"
        : "+f"(c[0]), "+f"(c[1]), "+f"(c[2]), "+f"(c[3])
        : "r"(a[0]), "r"(a[1]), "r"(a[2]), "r"(a[3]), "r"(b[0]), "r"(b[1]));
}

// pack two fp32 -> bf16x2 (lo = first arg, hi = second arg)
__device__ __forceinline__ uint32_t pack_bf16(float lo, float hi) {
    uint32_t r;
    asm("cvt.rn.bf16x2.f32 %0, %1, %2;" : "=r"(r) : "f"(hi), "f"(lo));
    return r;
}

__device__ __forceinline__ float bf16_rt(float v) {
    return __bfloat162float(__float2bfloat16(v));
}

// ---------------------------------------------------------------------------
// Split-bf16 GEMM via mma.sync: C[M,N] = (Ah+Al)[M,K] @ (Bh+Bl)^T,
// B given transposed [N,K]. CTA tile 128x128, BK=32, 256 threads (8 warps,
// warp tile m32 x n64). Smem rows padded to 40 halves for conflict-free
// ldmatrix. Product: Ah*Bh + Al*Bh + Ah*Bl.
// SPLIT=0: write fp32 C. SPLIT=1: write bf16 hi/lo (H, L).
// ---------------------------------------------------------------------------
#define GK 1024
#define TS 40
#define TILE_HALVES (128 * TS)       // 5120
#define TILE_BYTES (TILE_HALVES * 2) // 10240

template <int SPLIT>
__global__ __launch_bounds__(256) void gemm_mma_t(
    const __nv_bfloat16* __restrict__ Ah, const __nv_bfloat16* __restrict__ Al,
    const __nv_bfloat16* __restrict__ Bh, const __nv_bfloat16* __restrict__ Bl,
    float* __restrict__ C, __nv_bfloat16* __restrict__ H,
    __nv_bfloat16* __restrict__ L) {
    __shared__ __align__(16) __nv_bfloat16 sm[4][TILE_HALVES];

    const int tid = threadIdx.x;
    const int lane = tid & 31;
    const int wid = tid >> 5;
    const int wm = wid & 3;
    const int wn = wid >> 2;
    const int mBase = wm * 32;
    const int nBase = wn * 64;
    const int bm = blockIdx.y * 128;
    const int bn = blockIdx.x * 128;
    const uint32_t sb = smem_u32(sm);

    float c[2][8][4];
#pragma unroll
    for (int mt = 0; mt < 2; mt++)
#pragma unroll
        for (int nt = 0; nt < 8; nt++)
#pragma unroll
            for (int j = 0; j < 4; j++) c[mt][nt][j] = 0.0f;

    const int a_row = lane & 15;
    const int a_koff = (lane >> 4) * 8;
    const int b_nrow = ((lane >> 4) * 8) + (lane & 7);
    const int b_koff = ((lane >> 3) & 1) * 8;

    for (int ch = 0; ch < GK / 32; ch++) {
        const int k0 = ch * 32;
        const __nv_bfloat16* srcs[4] = {
            Ah + (size_t)bm * GK + k0, Al + (size_t)bm * GK + k0,
            Bh + (size_t)bn * GK + k0, Bl + (size_t)bn * GK + k0};
        __syncthreads();
#pragma unroll
        for (int t = 0; t < 4; t++) {
#pragma unroll
            for (int it = 0; it < 2; it++) {
                int idx = tid + it * 256;
                int r = idx >> 2, c16 = idx & 3;
                uint4 v = *(const uint4*)(srcs[t] + (size_t)r * GK + c16 * 8);
                *(uint4*)&sm[t][r * TS + c16 * 8] = v;
            }
        }
        __syncthreads();

#pragma unroll
        for (int ks = 0; ks < 2; ks++) {
            uint32_t aH[2][4], aL[2][4], b[8][2];
#pragma unroll
            for (int mt = 0; mt < 2; mt++) {
                uint32_t off = ((mBase + mt * 16 + a_row) * TS + ks * 16 + a_koff) * 2;
                ldsm_x4(sb + off, aH[mt][0], aH[mt][1], aH[mt][2], aH[mt][3]);
                ldsm_x4(sb + TILE_BYTES + off, aL[mt][0], aL[mt][1], aL[mt][2], aL[mt][3]);
            }
#pragma unroll
            for (int g = 0; g < 4; g++) {
                uint32_t off = ((nBase + g * 16 + b_nrow) * TS + ks * 16 + b_koff) * 2;
                ldsm_x4(sb + 2 * TILE_BYTES + off,
                        b[2 * g][0], b[2 * g][1], b[2 * g + 1][0], b[2 * g + 1][1]);
            }
#pragma unroll
            for (int mt = 0; mt < 2; mt++)
#pragma unroll
                for (int nt = 0; nt < 8; nt++) mma16816(c[mt][nt], aH[mt], b[nt]);
#pragma unroll
            for (int mt = 0; mt < 2; mt++)
#pragma unroll
                for (int nt = 0; nt < 8; nt++) mma16816(c[mt][nt], aL[mt], b[nt]);
#pragma unroll
            for (int g = 0; g < 4; g++) {
                uint32_t off = ((nBase + g * 16 + b_nrow) * TS + ks * 16 + b_koff) * 2;
                ldsm_x4(sb + 3 * TILE_BYTES + off,
                        b[2 * g][0], b[2 * g][1], b[2 * g + 1][0], b[2 * g + 1][1]);
            }
#pragma unroll
            for (int mt = 0; mt < 2; mt++)
#pragma unroll
                for (int nt = 0; nt < 8; nt++) mma16816(c[mt][nt], aH[mt], b[nt]);
        }
    }

#pragma unroll
    for (int mt = 0; mt < 2; mt++) {
#pragma unroll
        for (int half = 0; half < 2; half++) {
            int row = bm + mBase + mt * 16 + (lane >> 2) + half * 8;
#pragma unroll
            for (int nt = 0; nt < 8; nt++) {
                int col = bn + nBase + nt * 8 + (lane & 3) * 2;
                float v0 = c[mt][nt][2 * half];
                float v1 = c[mt][nt][2 * half + 1];
                if (SPLIT) {
                    size_t off = (size_t)row * D_MODEL + col;
                    *(uint32_t*)(H + off) = pack_bf16(bf16_rt(v0), bf16_rt(v1));
                    *(uint32_t*)(L + off) = pack_bf16(v0 - bf16_rt(v0), v1 - bf16_rt(v1));
                } else {
                    *(float2*)(C + (size_t)row * D_MODEL + col) = make_float2(v0, v1);
                }
            }
        }
    }
}

// ---------------------------------------------------------------------------
// Conversion kernels
// ---------------------------------------------------------------------------
__global__ __launch_bounds__(256) void split_fp32(const float* __restrict__ s,
                                                  __nv_bfloat16* __restrict__ h,
                                                  __nv_bfloat16* __restrict__ l) {
    int i = blockIdx.x * 256 + threadIdx.x;
    float4 v = ((const float4*)s)[i];
    float a[4] = {v.x, v.y, v.z, v.w};
    uint32_t hh[2], ll[2];
#pragma unroll
    for (int j = 0; j < 2; j++) {
        float h0 = bf16_rt(a[2 * j]), h1 = bf16_rt(a[2 * j + 1]);
        hh[j] = pack_bf16(h0, h1);
        ll[j] = pack_bf16(a[2 * j] - h0, a[2 * j + 1] - h1);
    }
    ((uint32_t*)h)[2 * i] = hh[0];
    ((uint32_t*)h)[2 * i + 1] = hh[1];
    ((uint32_t*)l)[2 * i] = ll[0];
    ((uint32_t*)l)[2 * i + 1] = ll[1];
}

__global__ __launch_bounds__(256) void transpose_split(const float* __restrict__ W,
                                                       __nv_bfloat16* __restrict__ Th,
                                                       __nv_bfloat16* __restrict__ Tl) {
    __shared__ float t[32][33];
    int x = blockIdx.x * 32 + threadIdx.x;
    int y0 = blockIdx.y * 32;
#pragma unroll
    for (int j = 0; j < 32; j += 8)
        t[threadIdx.y + j][threadIdx.x] = W[(size_t)(y0 + threadIdx.y + j) * D_MODEL + x];
    __syncthreads();
    int xo = blockIdx.y * 32 + threadIdx.x;
    int yo = blockIdx.x * 32;
#pragma unroll
    for (int j = 0; j < 32; j += 8) {
        float v = t[threadIdx.x][threadIdx.y + j];
        float hv = bf16_rt(v);
        Th[(size_t)(yo + threadIdx.y + j) * D_MODEL + xo] = __float2bfloat16(v);
        Tl[(size_t)(yo + threadIdx.y + j) * D_MODEL + xo] = __float2bfloat16(v - hv);
    }
}

// ---------------------------------------------------------------------------
// Tensor-core causal flash attention, split-bf16.
// Grid (32 qb, 32 b*h), 128 threads (4 warps, 16 q-rows each).
// Tiles 64x64, dh=64. Smem: Qh,Ql,Kh,Kl,Vh,Vl each [64][72] bf16 = 55296 B.
// S = QhKh + QlKh + QhKl ; PV = PhVh + PlVh + PhVl (P from regs, V via
// ldmatrix.trans).
// ---------------------------------------------------------------------------
#define TS2 72
#define ATILE (64 * TS2)  // 4608 halves

__global__ __launch_bounds__(128) void attn_tc() {
    extern __shared__ __align__(16) __nv_bfloat16 dsm[];
    const uint32_t sb = smem_u32(dsm);
    const uint32_t SQH = 0, SQL = ATILE * 2, SKH = 2 * ATILE * 2,
                   SKL = 3 * ATILE * 2, SVH = 4 * ATILE * 2, SVL = 5 * ATILE * 2;

    const int tid = threadIdx.x;
    const int lane = tid & 31;
    const int wq = tid >> 5;
    const int qb = gridDim.x - 1 - blockIdx.x;  // heavy blocks first
    const int bh = blockIdx.y;
    const int b = bh >> 4, h = bh & 15;

    // load Q tiles (rows qb*64.., head cols h*64..)
    {
        const size_t base = (size_t)(b * SEQ + qb * 64) * D_MODEL + h * 64;
#pragma unroll
        for (int it = 0; it < 4; it++) {
            int idx = tid + it * 128;
            int r = idx >> 3, c8 = idx & 7;
            *(uint4*)&dsm[r * TS2 + c8 * 8] =
                *(const uint4*)(g_qh + base + (size_t)r * D_MODEL + c8 * 8);
            *(uint4*)&dsm[ATILE + r * TS2 + c8 * 8] =
                *(const uint4*)(g_ql + base + (size_t)r * D_MODEL + c8 * 8);
        }
    }

    float O[8][4];
#pragma unroll
    for (int nt = 0; nt < 8; nt++)
#pragma unroll
        for (int j = 0; j < 4; j++) O[nt][j] = 0.0f;
    float mrow[2] = {-1e30f, -1e30f};
    float lrow[2] = {0.0f, 0.0f};

    const float scale = 0.03125f;  // 1/sqrt(1024)

    // fragment address components
    const uint32_t a_off = ((wq * 16 + (lane & 15)) * TS2 + (lane >> 4) * 8) * 2;
    const uint32_t b_off = ((((lane >> 4) * 8) + (lane & 7)) * TS2 + ((lane >> 3) & 1) * 8) * 2;
    const uint32_t v_off = ((((lane >> 3) & 1) * 8 + (lane & 7)) * TS2 + (lane >> 4) * 8) * 2;

    const int row0 = qb * 64 + wq * 16 + (lane >> 2);  // +8 for i=1

    for (int kb = 0; kb <= qb; kb++) {
        __syncthreads();
        // load K/V tiles
        {
            const size_t base = (size_t)(b * SEQ + kb * 64) * D_MODEL + h * 64;
#pragma unroll
            for (int it = 0; it < 4; it++) {
                int idx = tid + it * 128;
                int r = idx >> 3, c8 = idx & 7;
                size_t g = base + (size_t)r * D_MODEL + c8 * 8;
                uint32_t so = r * TS2 + c8 * 8;
                *(uint4*)&dsm[2 * ATILE + so] = *(const uint4*)(g_kh + g);
                *(uint4*)&dsm[3 * ATILE + so] = *(const uint4*)(g_kl + g);
                *(uint4*)&dsm[4 * ATILE + so] = *(const uint4*)(g_vh + g);
                *(uint4*)&dsm[5 * ATILE + so] = *(const uint4*)(g_vl + g);
            }
        }
        __syncthreads();

        // ---- S = Q @ K^T (split) ----
        float s[8][4];
#pragma unroll
        for (int nt = 0; nt < 8; nt++)
#pragma unroll
            for (int j = 0; j < 4; j++) s[nt][j] = 0.0f;

#pragma unroll
        for (int ks = 0; ks < 4; ks++) {
            uint32_t aH[4], aL[4], bk[8][2];
            ldsm_x4(sb + SQH + a_off + ks * 32, aH[0], aH[1], aH[2], aH[3]);
            ldsm_x4(sb + SQL + a_off + ks * 32, aL[0], aL[1], aL[2], aL[3]);
#pragma unroll
            for (int g = 0; g < 4; g++)
                ldsm_x4(sb + SKH + b_off + g * 16 * TS2 * 2 + ks * 32,
                        bk[2 * g][0], bk[2 * g][1], bk[2 * g + 1][0], bk[2 * g + 1][1]);
#pragma unroll
            for (int nt = 0; nt < 8; nt++) mma16816(s[nt], aH, bk[nt]);
#pragma unroll
            for (int nt = 0; nt < 8; nt++) mma16816(s[nt], aL, bk[nt]);
#pragma unroll
            for (int g = 0; g < 4; g++)
                ldsm_x4(sb + SKL + b_off + g * 16 * TS2 * 2 + ks * 32,
                        bk[2 * g][0], bk[2 * g][1], bk[2 * g + 1][0], bk[2 * g + 1][1]);
#pragma unroll
            for (int nt = 0; nt < 8; nt++) mma16816(s[nt], aH, bk[nt]);
        }

        // ---- scale + mask + online softmax ----
        const bool diag = (kb == qb);
#pragma unroll
        for (int i = 0; i < 2; i++) {
            const int rg = row0 + i * 8;
            float mx = -1e30f;
#pragma unroll
            for (int nt = 0; nt < 8; nt++) {
#pragma unroll
                for (int j = 0; j < 2; j++) {
                    int cg = kb * 64 + nt * 8 + (lane & 3) * 2 + j;
                    float v = s[nt][2 * i + j] * scale;
                    if (diag && cg > rg) v = -1e30f;
                    s[nt][2 * i + j] = v;
                    mx = fmaxf(mx, v);
                }
            }
            mx = fmaxf(mx, __shfl_xor_sync(0xffffffffu, mx, 1));
            mx = fmaxf(mx, __shfl_xor_sync(0xffffffffu, mx, 2));
            float mn = fmaxf(mrow[i], mx);
            float alpha = __expf(mrow[i] - mn);
            mrow[i] = mn;
            float rs = 0.0f;
#pragma unroll
            for (int nt = 0; nt < 8; nt++) {
#pragma unroll
                for (int j = 0; j < 2; j++) {
                    float p = __expf(s[nt][2 * i + j] - mn);
                    s[nt][2 * i + j] = p;
                    rs += p;
                }
            }
            rs += __shfl_xor_sync(0xffffffffu, rs, 1);
            rs += __shfl_xor_sync(0xffffffffu, rs, 2);
            lrow[i] = lrow[i] * alpha + rs;
#pragma unroll
            for (int nt = 0; nt < 8; nt++) {
                O[nt][2 * i] *= alpha;
                O[nt][2 * i + 1] *= alpha;
            }
        }

        // ---- O += P @ V (split; P from registers, V via ldmatrix.trans) ----
#pragma unroll
        for (int g = 0; g < 4; g++) {
            uint32_t pH[4], pL[4];
#pragma unroll
            for (int q2 = 0; q2 < 2; q2++) {      // tiles 2g, 2g+1 -> a pairs
#pragma unroll
                for (int half = 0; half < 2; half++) {
                    float v0 = s[2 * g + q2][2 * half];
                    float v1 = s[2 * g + q2][2 * half + 1];
                    float h0 = bf16_rt(v0), h1 = bf16_rt(v1);
                    pH[2 * q2 + half] = pack_bf16(h0, h1);
                    pL[2 * q2 + half] = pack_bf16(v0 - h0, v1 - h1);
                }
            }
            uint32_t bv[8][2];
#pragma unroll
            for (int gn = 0; gn < 4; gn++)
                ldsm_x4_t(sb + SVH + v_off + (g * 16 * TS2 + gn * 16) * 2,
                          bv[2 * gn][0], bv[2 * gn][1], bv[2 * gn + 1][0], bv[2 * gn + 1][1]);
#pragma unroll
            for (int nt = 0; nt < 8; nt++) mma16816(O[nt], pH, bv[nt]);
#pragma unroll
            for (int nt = 0; nt < 8; nt++) mma16816(O[nt], pL, bv[nt]);
#pragma unroll
            for (int gn = 0; gn < 4; gn++)
                ldsm_x4_t(sb + SVL + v_off + (g * 16 * TS2 + gn * 16) * 2,
                          bv[2 * gn][0], bv[2 * gn][1], bv[2 * gn + 1][0], bv[2 * gn + 1][1]);
#pragma unroll
            for (int nt = 0; nt < 8; nt++) mma16816(O[nt], pH, bv[nt]);
        }
    }

    // ---- epilogue: normalize, write split bf16 ----
#pragma unroll
    for (int i = 0; i < 2; i++) {
        float inv = 1.0f / lrow[i];
        size_t row = (size_t)(b * SEQ) + row0 + i * 8;
#pragma unroll
        for (int nt = 0; nt < 8; nt++) {
            size_t off = row * D_MODEL + h * 64 + nt * 8 + (lane & 3) * 2;
            float v0 = O[nt][2 * i] * inv;
            float v1 = O[nt][2 * i + 1] * inv;
            float h0 = bf16_rt(v0), h1 = bf16_rt(v1);
            *(uint32_t*)(g_ah + off) = pack_bf16(h0, h1);
            *(uint32_t*)(g_al + off) = pack_bf16(v0 - h0, v1 - h1);
        }
    }
}

// ---------------------------------------------------------------------------
// kernel_launch: x, qw, kw, vw, ow (fp32)
// ---------------------------------------------------------------------------
extern "C" void kernel_launch(void* const* d_in, const int* in_sizes, int n_in,
                              void* d_out, int out_size) {
    const float* x = (const float*)d_in[0];
    const float* w[4] = {(const float*)d_in[1], (const float*)d_in[2],
                         (const float*)d_in[3], (const float*)d_in[4]};
    float* out = (float*)d_out;

    __nv_bfloat16 *xh, *xl, *qh, *ql, *kh, *kl, *vh, *vl, *ah, *al, *wh, *wl;
    cudaGetSymbolAddress((void**)&xh, g_xh);
    cudaGetSymbolAddress((void**)&xl, g_xl);
    cudaGetSymbolAddress((void**)&qh, g_qh);
    cudaGetSymbolAddress((void**)&ql, g_ql);
    cudaGetSymbolAddress((void**)&kh, g_kh);
    cudaGetSymbolAddress((void**)&kl, g_kl);
    cudaGetSymbolAddress((void**)&vh, g_vh);
    cudaGetSymbolAddress((void**)&vl, g_vl);
    cudaGetSymbolAddress((void**)&ah, g_ah);
    cudaGetSymbolAddress((void**)&al, g_al);
    cudaGetSymbolAddress((void**)&wh, g_wh);
    cudaGetSymbolAddress((void**)&wl, g_wl);

    const int attn_smem = 6 * ATILE * 2;  // 55296
    cudaFuncSetAttribute(attn_tc, cudaFuncAttributeMaxDynamicSharedMemorySize,
                         attn_smem);

    // 1. split x
    split_fp32<<<(ROWS * D_MODEL / 4) / 256, 256>>>(x, xh, xl);
    // 2. transpose+split weights
    for (int i = 0; i < 4; i++)
        transpose_split<<<dim3(32, 32), dim3(32, 8)>>>(
            w[i], wh + (size_t)i * D_MODEL * D_MODEL, wl + (size_t)i * D_MODEL * D_MODEL);

    // 3. Q/K/V projections with split-bf16 epilogue
    dim3 ggrid(D_MODEL / 128, ROWS / 128);
    gemm_mma_t<1><<<ggrid, 256>>>(xh, xl, wh, wl, nullptr, qh, ql);
    gemm_mma_t<1><<<ggrid, 256>>>(xh, xl, wh + 1u * D_MODEL * D_MODEL,
                                  wl + 1u * D_MODEL * D_MODEL, nullptr, kh, kl);
    gemm_mma_t<1><<<ggrid, 256>>>(xh, xl, wh + 2u * D_MODEL * D_MODEL,
                                  wl + 2u * D_MODEL * D_MODEL, nullptr, vh, vl);

    // 4. tensor-core attention (writes ah/al directly)
    dim3 agrid(SEQ / 64, BATCH * N_HEADS);
    attn_tc<<<agrid, 128, attn_smem>>>();

    // 5. output projection (fp32 epilogue to d_out)
    gemm_mma_t<0><<<ggrid, 256>>>(ah, al, wh + 3u * D_MODEL * D_MODEL,
                                  wl + 3u * D_MODEL * D_MODEL, out, nullptr, nullptr);
}

// round 7
// speedup vs baseline: 4.1062x; 1.1375x over previous
#include <cuda_runtime.h>
#include <cuda_bf16.h>
#include <cstdint>
#include <cstddef>

#define D_MODEL 1024
#define N_HEADS 16
#define HEAD_DIM 64
#define BATCH 2
#define SEQ 2048
#define ROWS (BATCH * SEQ)   // 4096

// ---------------- scratch (__device__ globals; allocation-free rule) -------
__device__ __nv_bfloat16 g_xh[ROWS * D_MODEL];
__device__ __nv_bfloat16 g_xl[ROWS * D_MODEL];
__device__ __nv_bfloat16 g_qh[ROWS * D_MODEL];
__device__ __nv_bfloat16 g_ql[ROWS * D_MODEL];
__device__ __nv_bfloat16 g_kh[ROWS * D_MODEL];
__device__ __nv_bfloat16 g_kl[ROWS * D_MODEL];
__device__ __nv_bfloat16 g_vh[ROWS * D_MODEL];
__device__ __nv_bfloat16 g_vl[ROWS * D_MODEL];
__device__ __nv_bfloat16 g_ah[ROWS * D_MODEL];
__device__ __nv_bfloat16 g_al[ROWS * D_MODEL];
__device__ __nv_bfloat16 g_wh[4 * D_MODEL * D_MODEL];  // transposed [N,K]
__device__ __nv_bfloat16 g_wl[4 * D_MODEL * D_MODEL];

// ---------------- helpers --------------------------------------------------
__device__ __forceinline__ uint32_t smem_u32(const void* p) {
    uint32_t a;
    asm("{ .reg .u64 t; cvta.to.shared.u64 t, %1; cvt.u32.u64 %0, t; }"
        : "=r"(a) : "l"(p));
    return a;
}

__device__ __forceinline__ void cp16(uint32_t s, const void* g) {
    asm volatile("cp.async.cg.shared.global [%0], [%1], 16;" :: "r"(s), "l"(g));
}
#define CP_COMMIT() asm volatile("cp.async.commit_group;" ::: "memory")
#define CP_WAIT(n)  asm volatile("cp.async.wait_group %0;" :: "n"(n) : "memory")

__device__ __forceinline__ void ldsm_x4(uint32_t addr, uint32_t& r0, uint32_t& r1,
                                        uint32_t& r2, uint32_t& r3) {
    asm volatile("ldmatrix.sync.aligned.m8n8.x4.shared.b16 {%0,%1,%2,%3}, [%4];"
                 : "=r"(r0), "=r"(r1), "=r"(r2), "=r"(r3) : "r"(addr));
}

__device__ __forceinline__ void ldsm_x4_t(uint32_t addr, uint32_t& r0, uint32_t& r1,
                                          uint32_t& r2, uint32_t& r3) {
    asm volatile("ldmatrix.sync.aligned.m8n8.x4.trans.shared.b16 {%0,%1,%2,%3}, [%4];"
                 : "=r"(r0), "=r"(r1), "=r"(r2), "=r"(r3) : "r"(addr));
}

__device__ __forceinline__ void mma16816(float* c, const uint32_t* a, const uint32_t* b) {
    asm volatile(
        "mma.sync.aligned.m16n8k16.row.col.f32.bf16.bf16.f32 "
        "{%0,%1,%2,%3},{%4,%5,%6,%7},{%8,%9},{%0,%1,%2,%3};"
        : "+f"(c[0]), "+f"(c[1]), "+f"(c[2]), "+f"(c[3])
        : "r"(a[0]), "r"(a[1]), "r"(a[2]), "r"(a[3]), "r"(b[0]), "r"(b[1]));
}

__device__ __forceinline__ uint32_t pack_bf16(float lo, float hi) {
    uint32_t r;
    asm("cvt.rn.bf16x2.f32 %0, %1, %2;" : "=r"(r) : "f"(hi), "f"(lo));
    return r;
}

__device__ __forceinline__ float bf16_rt(float v) {
    return __bfloat162float(__float2bfloat16(v));
}

// ---------------------------------------------------------------------------
// Pipelined split-bf16 GEMM (cp.async double-buffer).
// C[M,N] = (Ah+Al)[M,K] @ (Bh+Bl)^T, B transposed [N,K]. CTA tile 128x128,
// BK=32, 256 threads, warp tile m32 x n64. Product AhBh + AlBh + AhBl.
// QKV=1: grid.z selects weight/output from device globals, split epilogue.
// QKV=0: fp32 epilogue to C.
// ---------------------------------------------------------------------------
#define GK 1024
#define NCH (GK / 32)                // 32
#define TS 40
#define TILE_HALVES (128 * TS)       // 5120
#define TILE_BYTES (TILE_HALVES * 2) // 10240
#define STAGE_BYTES (4 * TILE_BYTES) // 40960
#define GEMM_SMEM (2 * STAGE_BYTES)  // 81920

template <int QKV>
__global__ __launch_bounds__(256, 1) void gemm_pipe(
    const __nv_bfloat16* __restrict__ Ah, const __nv_bfloat16* __restrict__ Al,
    const __nv_bfloat16* __restrict__ Bh, const __nv_bfloat16* __restrict__ Bl,
    float* __restrict__ C, __nv_bfloat16* __restrict__ H,
    __nv_bfloat16* __restrict__ L) {
    extern __shared__ __align__(16) char gsm[];
    if (QKV) {
        const size_t zo = (size_t)blockIdx.z * D_MODEL * D_MODEL;
        Ah = g_xh; Al = g_xl;
        Bh = g_wh + zo; Bl = g_wl + zo;
        H = blockIdx.z == 0 ? g_qh : blockIdx.z == 1 ? g_kh : g_vh;
        L = blockIdx.z == 0 ? g_ql : blockIdx.z == 1 ? g_kl : g_vl;
    }

    const int tid = threadIdx.x;
    const int lane = tid & 31;
    const int wid = tid >> 5;
    const int wm = wid & 3;
    const int wn = wid >> 2;
    const int mBase = wm * 32;
    const int nBase = wn * 64;
    const int bm = blockIdx.y * 128;
    const int bn = blockIdx.x * 128;
    const uint32_t sb = smem_u32(gsm);

    const int ld_r = tid >> 2, ld_c = (tid & 3) * 8;  // 16B chunk 0 of 2

    float c[2][8][4];
#pragma unroll
    for (int mt = 0; mt < 2; mt++)
#pragma unroll
        for (int nt = 0; nt < 8; nt++)
#pragma unroll
            for (int j = 0; j < 4; j++) c[mt][nt][j] = 0.0f;

    const int a_row = lane & 15;
    const int a_koff = (lane >> 4) * 8;
    const int b_nrow = ((lane >> 4) * 8) + (lane & 7);
    const int b_koff = ((lane >> 3) & 1) * 8;

    // -------- async chunk loader ----------
    auto issue = [&](int ch, int stage) {
        const int k0 = ch * 32;
        const __nv_bfloat16* srcs[4] = {
            Ah + (size_t)bm * GK + k0, Al + (size_t)bm * GK + k0,
            Bh + (size_t)bn * GK + k0, Bl + (size_t)bn * GK + k0};
        const uint32_t sbase = sb + stage * STAGE_BYTES;
#pragma unroll
        for (int t = 0; t < 4; t++) {
#pragma unroll
            for (int it = 0; it < 2; it++) {
                int r = ld_r + it * 64;
                cp16(sbase + t * TILE_BYTES + (r * TS + ld_c) * 2,
                     srcs[t] + (size_t)r * GK + ld_c);
            }
        }
        CP_COMMIT();
    };

    issue(0, 0);

    for (int ch = 0; ch < NCH; ch++) {
        if (ch + 1 < NCH) {
            issue(ch + 1, (ch + 1) & 1);
            CP_WAIT(1);
        } else {
            CP_WAIT(0);
        }
        __syncthreads();
        const uint32_t base = sb + (ch & 1) * STAGE_BYTES;

#pragma unroll
        for (int ks = 0; ks < 2; ks++) {
            uint32_t aH[2][4], aL[2][4], b[8][2];
#pragma unroll
            for (int mt = 0; mt < 2; mt++) {
                uint32_t off = ((mBase + mt * 16 + a_row) * TS + ks * 16 + a_koff) * 2;
                ldsm_x4(base + off, aH[mt][0], aH[mt][1], aH[mt][2], aH[mt][3]);
                ldsm_x4(base + TILE_BYTES + off, aL[mt][0], aL[mt][1], aL[mt][2], aL[mt][3]);
            }
#pragma unroll
            for (int g = 0; g < 4; g++) {
                uint32_t off = ((nBase + g * 16 + b_nrow) * TS + ks * 16 + b_koff) * 2;
                ldsm_x4(base + 2 * TILE_BYTES + off,
                        b[2 * g][0], b[2 * g][1], b[2 * g + 1][0], b[2 * g + 1][1]);
            }
#pragma unroll
            for (int mt = 0; mt < 2; mt++)
#pragma unroll
                for (int nt = 0; nt < 8; nt++) mma16816(c[mt][nt], aH[mt], b[nt]);
#pragma unroll
            for (int mt = 0; mt < 2; mt++)
#pragma unroll
                for (int nt = 0; nt < 8; nt++) mma16816(c[mt][nt], aL[mt], b[nt]);
#pragma unroll
            for (int g = 0; g < 4; g++) {
                uint32_t off = ((nBase + g * 16 + b_nrow) * TS + ks * 16 + b_koff) * 2;
                ldsm_x4(base + 3 * TILE_BYTES + off,
                        b[2 * g][0], b[2 * g][1], b[2 * g + 1][0], b[2 * g + 1][1]);
            }
#pragma unroll
            for (int mt = 0; mt < 2; mt++)
#pragma unroll
                for (int nt = 0; nt < 8; nt++) mma16816(c[mt][nt], aH[mt], b[nt]);
        }
        __syncthreads();
    }

#pragma unroll
    for (int mt = 0; mt < 2; mt++) {
#pragma unroll
        for (int half = 0; half < 2; half++) {
            int row = bm + mBase + mt * 16 + (lane >> 2) + half * 8;
#pragma unroll
            for (int nt = 0; nt < 8; nt++) {
                int col = bn + nBase + nt * 8 + (lane & 3) * 2;
                float v0 = c[mt][nt][2 * half];
                float v1 = c[mt][nt][2 * half + 1];
                if (QKV) {
                    size_t off = (size_t)row * D_MODEL + col;
                    float h0 = bf16_rt(v0), h1 = bf16_rt(v1);
                    *(uint32_t*)(H + off) = pack_bf16(h0, h1);
                    *(uint32_t*)(L + off) = pack_bf16(v0 - h0, v1 - h1);
                } else {
                    *(float2*)(C + (size_t)row * D_MODEL + col) = make_float2(v0, v1);
                }
            }
        }
    }
}

// ---------------------------------------------------------------------------
// Conversion kernels
// ---------------------------------------------------------------------------
__global__ __launch_bounds__(256) void split_fp32(const float* __restrict__ s,
                                                  __nv_bfloat16* __restrict__ h,
                                                  __nv_bfloat16* __restrict__ l) {
    int i = blockIdx.x * 256 + threadIdx.x;
    float4 v = ((const float4*)s)[i];
    float a[4] = {v.x, v.y, v.z, v.w};
    uint32_t hh[2], ll[2];
#pragma unroll
    for (int j = 0; j < 2; j++) {
        float h0 = bf16_rt(a[2 * j]), h1 = bf16_rt(a[2 * j + 1]);
        hh[j] = pack_bf16(h0, h1);
        ll[j] = pack_bf16(a[2 * j] - h0, a[2 * j + 1] - h1);
    }
    ((uint32_t*)h)[2 * i] = hh[0];
    ((uint32_t*)h)[2 * i + 1] = hh[1];
    ((uint32_t*)l)[2 * i] = ll[0];
    ((uint32_t*)l)[2 * i + 1] = ll[1];
}

__global__ __launch_bounds__(256) void transpose_split4(const float* __restrict__ w0,
                                                        const float* __restrict__ w1,
                                                        const float* __restrict__ w2,
                                                        const float* __restrict__ w3) {
    __shared__ float t[32][33];
    const int z = blockIdx.z;
    const float* W = z == 0 ? w0 : z == 1 ? w1 : z == 2 ? w2 : w3;
    __nv_bfloat16* Th = g_wh + (size_t)z * D_MODEL * D_MODEL;
    __nv_bfloat16* Tl = g_wl + (size_t)z * D_MODEL * D_MODEL;

    int x = blockIdx.x * 32 + threadIdx.x;
    int y0 = blockIdx.y * 32;
#pragma unroll
    for (int j = 0; j < 32; j += 8)
        t[threadIdx.y + j][threadIdx.x] = W[(size_t)(y0 + threadIdx.y + j) * D_MODEL + x];
    __syncthreads();
    int xo = blockIdx.y * 32 + threadIdx.x;
    int yo = blockIdx.x * 32;
#pragma unroll
    for (int j = 0; j < 32; j += 8) {
        float v = t[threadIdx.x][threadIdx.y + j];
        float hv = bf16_rt(v);
        Th[(size_t)(yo + threadIdx.y + j) * D_MODEL + xo] = __float2bfloat16(v);
        Tl[(size_t)(yo + threadIdx.y + j) * D_MODEL + xo] = __float2bfloat16(v - hv);
    }
}

// ---------------------------------------------------------------------------
// Tensor-core causal flash attention, split-bf16, cp.async KV prefetch.
// Grid (32 qb, 32 b*h), 128 threads. Tiles 64x64, dh=64.
// Smem: Q(h,l) + 2 stages x KV(kh,kl,vh,vl); each tile 64x72 bf16 = 9216 B.
// Total 10 * 9216 = 92160 B. S = QhKh+QlKh+QhKl ; PV = PhVh+PlVh+PhVl.
// ---------------------------------------------------------------------------
#define TS2 72
#define ATILE_B (64 * TS2 * 2)       // 9216 bytes per tile
#define KV_STAGE (4 * ATILE_B)       // 36864
#define ATTN_SMEM (2 * ATILE_B + 2 * KV_STAGE)  // 92160

__global__ __launch_bounds__(128, 1) void attn_tc() {
    extern __shared__ __align__(16) char asmc[];
    const uint32_t sb = smem_u32(asmc);

    const int tid = threadIdx.x;
    const int lane = tid & 31;
    const int wq = tid >> 5;
    const int qb = gridDim.x - 1 - blockIdx.x;  // heavy blocks first
    const int bh = blockIdx.y;
    const int b = bh >> 4, h = bh & 15;

    const int ld_r = tid >> 1, ld_c = (tid & 1) * 8;  // 64 rows x 2 chunks/16B... (8 halves)

    // ---- Q loads (group 0) ----
    {
        const size_t base = (size_t)(b * SEQ + qb * 64) * D_MODEL + h * 64;
#pragma unroll
        for (int it = 0; it < 4; it++) {
            int idx = tid + it * 128;
            int r = idx >> 3, c8 = (idx & 7) * 8;
            size_t g = base + (size_t)r * D_MODEL + c8;
            uint32_t so = (r * TS2 + c8) * 2;
            cp16(sb + so, g_qh + g);
            cp16(sb + ATILE_B + so, g_ql + g);
        }
        CP_COMMIT();
    }

    auto issue_kv = [&](int kb, int stage) {
        const size_t base = (size_t)(b * SEQ + kb * 64) * D_MODEL + h * 64;
        const uint32_t kvb = sb + 2 * ATILE_B + stage * KV_STAGE;
#pragma unroll
        for (int it = 0; it < 4; it++) {
            int idx = tid + it * 128;
            int r = idx >> 3, c8 = (idx & 7) * 8;
            size_t g = base + (size_t)r * D_MODEL + c8;
            uint32_t so = (r * TS2 + c8) * 2;
            cp16(kvb + so, g_kh + g);
            cp16(kvb + ATILE_B + so, g_kl + g);
            cp16(kvb + 2 * ATILE_B + so, g_vh + g);
            cp16(kvb + 3 * ATILE_B + so, g_vl + g);
        }
        CP_COMMIT();
    };

    issue_kv(0, 0);

    float O[8][4];
#pragma unroll
    for (int nt = 0; nt < 8; nt++)
#pragma unroll
        for (int j = 0; j < 4; j++) O[nt][j] = 0.0f;
    float mrow[2] = {-1e30f, -1e30f};
    float lrow[2] = {0.0f, 0.0f};

    const float scale = 0.03125f;

    const uint32_t a_off = ((wq * 16 + (lane & 15)) * TS2 + (lane >> 4) * 8) * 2;
    const uint32_t b_off = ((((lane >> 4) * 8) + (lane & 7)) * TS2 + ((lane >> 3) & 1) * 8) * 2;
    const uint32_t v_off = ((((lane >> 3) & 1) * 8 + (lane & 7)) * TS2 + (lane >> 4) * 8) * 2;

    const int row0 = qb * 64 + wq * 16 + (lane >> 2);
    (void)ld_r; (void)ld_c;

    for (int kb = 0; kb <= qb; kb++) {
        if (kb < qb) {
            issue_kv(kb + 1, (kb + 1) & 1);
            CP_WAIT(1);
        } else {
            CP_WAIT(0);
        }
        __syncthreads();

        const uint32_t kvb = sb + 2 * ATILE_B + (kb & 1) * KV_STAGE;
        const uint32_t SKH = kvb, SKL = kvb + ATILE_B,
                       SVH = kvb + 2 * ATILE_B, SVL = kvb + 3 * ATILE_B;

        // ---- S = Q @ K^T (split) ----
        float s[8][4];
#pragma unroll
        for (int nt = 0; nt < 8; nt++)
#pragma unroll
            for (int j = 0; j < 4; j++) s[nt][j] = 0.0f;

#pragma unroll
        for (int ks = 0; ks < 4; ks++) {
            uint32_t aH[4], aL[4], bk[8][2];
            ldsm_x4(sb + a_off + ks * 32, aH[0], aH[1], aH[2], aH[3]);
            ldsm_x4(sb + ATILE_B + a_off + ks * 32, aL[0], aL[1], aL[2], aL[3]);
#pragma unroll
            for (int g = 0; g < 4; g++)
                ldsm_x4(SKH + b_off + g * 16 * TS2 * 2 + ks * 32,
                        bk[2 * g][0], bk[2 * g][1], bk[2 * g + 1][0], bk[2 * g + 1][1]);
#pragma unroll
            for (int nt = 0; nt < 8; nt++) mma16816(s[nt], aH, bk[nt]);
#pragma unroll
            for (int nt = 0; nt < 8; nt++) mma16816(s[nt], aL, bk[nt]);
#pragma unroll
            for (int g = 0; g < 4; g++)
                ldsm_x4(SKL + b_off + g * 16 * TS2 * 2 + ks * 32,
                        bk[2 * g][0], bk[2 * g][1], bk[2 * g + 1][0], bk[2 * g + 1][1]);
#pragma unroll
            for (int nt = 0; nt < 8; nt++) mma16816(s[nt], aH, bk[nt]);
        }

        // ---- scale + mask + online softmax ----
        const bool diag = (kb == qb);
#pragma unroll
        for (int i = 0; i < 2; i++) {
            const int rg = row0 + i * 8;
            float mx = -1e30f;
#pragma unroll
            for (int nt = 0; nt < 8; nt++) {
#pragma unroll
                for (int j = 0; j < 2; j++) {
                    int cg = kb * 64 + nt * 8 + (lane & 3) * 2 + j;
                    float v = s[nt][2 * i + j] * scale;
                    if (diag && cg > rg) v = -1e30f;
                    s[nt][2 * i + j] = v;
                    mx = fmaxf(mx, v);
                }
            }
            mx = fmaxf(mx, __shfl_xor_sync(0xffffffffu, mx, 1));
            mx = fmaxf(mx, __shfl_xor_sync(0xffffffffu, mx, 2));
            float mn = fmaxf(mrow[i], mx);
            float alpha = __expf(mrow[i] - mn);
            mrow[i] = mn;
            float rs = 0.0f;
#pragma unroll
            for (int nt = 0; nt < 8; nt++) {
#pragma unroll
                for (int j = 0; j < 2; j++) {
                    float p = __expf(s[nt][2 * i + j] - mn);
                    s[nt][2 * i + j] = p;
                    rs += p;
                }
            }
            rs += __shfl_xor_sync(0xffffffffu, rs, 1);
            rs += __shfl_xor_sync(0xffffffffu, rs, 2);
            lrow[i] = lrow[i] * alpha + rs;
#pragma unroll
            for (int nt = 0; nt < 8; nt++) {
                O[nt][2 * i] *= alpha;
                O[nt][2 * i + 1] *= alpha;
            }
        }

        // ---- O += P @ V (split) ----
#pragma unroll
        for (int g = 0; g < 4; g++) {
            uint32_t pH[4], pL[4];
#pragma unroll
            for (int q2 = 0; q2 < 2; q2++) {
#pragma unroll
                for (int half = 0; half < 2; half++) {
                    float v0 = s[2 * g + q2][2 * half];
                    float v1 = s[2 * g + q2][2 * half + 1];
                    float h0 = bf16_rt(v0), h1 = bf16_rt(v1);
                    pH[2 * q2 + half] = pack_bf16(h0, h1);
                    pL[2 * q2 + half] = pack_bf16(v0 - h0, v1 - h1);
                }
            }
            uint32_t bv[8][2];
#pragma unroll
            for (int gn = 0; gn < 4; gn++)
                ldsm_x4_t(SVH + v_off + (g * 16 * TS2 + gn * 16) * 2,
                          bv[2 * gn][0], bv[2 * gn][1], bv[2 * gn + 1][0], bv[2 * gn + 1][1]);
#pragma unroll
            for (int nt = 0; nt < 8; nt++) mma16816(O[nt], pH, bv[nt]);
#pragma unroll
            for (int nt = 0; nt < 8; nt++) mma16816(O[nt], pL, bv[nt]);
#pragma unroll
            for (int gn = 0; gn < 4; gn++)
                ldsm_x4_t(SVL + v_off + (g * 16 * TS2 + gn * 16) * 2,
                          bv[2 * gn][0], bv[2 * gn][1], bv[2 * gn + 1][0], bv[2 * gn + 1][1]);
#pragma unroll
            for (int nt = 0; nt < 8; nt++) mma16816(O[nt], pH, bv[nt]);
        }
        __syncthreads();
    }

    // ---- epilogue ----
#pragma unroll
    for (int i = 0; i < 2; i++) {
        float inv = 1.0f / lrow[i];
        size_t row = (size_t)(b * SEQ) + row0 + i * 8;
#pragma unroll
        for (int nt = 0; nt < 8; nt++) {
            size_t off = row * D_MODEL + h * 64 + nt * 8 + (lane & 3) * 2;
            float v0 = O[nt][2 * i] * inv;
            float v1 = O[nt][2 * i + 1] * inv;
            float h0 = bf16_rt(v0), h1 = bf16_rt(v1);
            *(uint32_t*)(g_ah + off) = pack_bf16(h0, h1);
            *(uint32_t*)(g_al + off) = pack_bf16(v0 - h0, v1 - h1);
        }
    }
}

// ---------------------------------------------------------------------------
// kernel_launch: x, qw, kw, vw, ow (fp32)
// ---------------------------------------------------------------------------
extern "C" void kernel_launch(void* const* d_in, const int* in_sizes, int n_in,
                              void* d_out, int out_size) {
    const float* x = (const float*)d_in[0];
    float* out = (float*)d_out;

    __nv_bfloat16 *xh, *xl, *ah, *al, *wh, *wl;
    cudaGetSymbolAddress((void**)&xh, g_xh);
    cudaGetSymbolAddress((void**)&xl, g_xl);
    cudaGetSymbolAddress((void**)&ah, g_ah);
    cudaGetSymbolAddress((void**)&al, g_al);
    cudaGetSymbolAddress((void**)&wh, g_wh);
    cudaGetSymbolAddress((void**)&wl, g_wl);

    cudaFuncSetAttribute(gemm_pipe<1>, cudaFuncAttributeMaxDynamicSharedMemorySize,
                         GEMM_SMEM);
    cudaFuncSetAttribute(gemm_pipe<0>, cudaFuncAttributeMaxDynamicSharedMemorySize,
                         GEMM_SMEM);
    cudaFuncSetAttribute(attn_tc, cudaFuncAttributeMaxDynamicSharedMemorySize,
                         ATTN_SMEM);

    // 1. split x into bf16 hi/lo
    split_fp32<<<(ROWS * D_MODEL / 4) / 256, 256>>>(x, xh, xl);
    // 2. transpose+split all 4 weights (one launch)
    transpose_split4<<<dim3(32, 32, 4), dim3(32, 8)>>>(
        (const float*)d_in[1], (const float*)d_in[2],
        (const float*)d_in[3], (const float*)d_in[4]);

    // 3. fused Q/K/V projections (pipelined, one launch)
    gemm_pipe<1><<<dim3(D_MODEL / 128, ROWS / 128, 3), 256, GEMM_SMEM>>>(
        nullptr, nullptr, nullptr, nullptr, nullptr, nullptr, nullptr);

    // 4. tensor-core attention (writes ah/al)
    attn_tc<<<dim3(SEQ / 64, BATCH * N_HEADS), 128, ATTN_SMEM>>>();

    // 5. output projection (fp32 epilogue to d_out)
    gemm_pipe<0><<<dim3(D_MODEL / 128, ROWS / 128, 1), 256, GEMM_SMEM>>>(
        ah, al, wh + 3u * D_MODEL * D_MODEL, wl + 3u * D_MODEL * D_MODEL,
        out, nullptr, nullptr);
}